// round 14
// baseline (speedup 1.0000x reference)
#include <cuda_runtime.h>
#include <stdint.h>

// Problem constants (fixed by the reference: z[100000,16], cluster[16,16], 100 bins)
#define NMAX 100000
#define F    16
#define CNUM 16
#define NB   100
#define NE   101
#define TPAD 20   // floats per (f,bs) row in the lookup table (bank-conflict padding)

// ---------------- device scratch (no allocations allowed) ----------------
__device__ unsigned int g_lo_bits[F];
__device__ unsigned int g_hi_bits[F];
__device__ float        g_edges[F * NE];
__device__ int          g_counts[F * NB];
__device__ int          g_cum[F * NB];
__device__ __align__(16) unsigned char g_sbins[NMAX * F];
__device__ unsigned char g_cbins[CNUM * F];
__device__ __align__(16) float g_table[F * NB * TPAD];

// order-preserving float <-> uint map (handles negatives) for atomic min/max
__device__ __forceinline__ unsigned f2ord(float f) {
    unsigned u = __float_as_uint(f);
    return (u & 0x80000000u) ? ~u : (u | 0x80000000u);
}
__device__ __forceinline__ float ord2f(unsigned u) {
    return (u & 0x80000000u) ? __uint_as_float(u & 0x7fffffffu)
                             : __uint_as_float(~u);
}

// ---------------- 1) init sentinels + zero histogram ----------------
__global__ void k_init() {
    int i = blockIdx.x * blockDim.x + threadIdx.x;
    if (i < F * NB) g_counts[i] = 0;
    if (i < F) { g_lo_bits[i] = 0xFFFFFFFFu; g_hi_bits[i] = 0u; }
}

// ---------------- 2) per-feature min/max over combined = [z; cluster] ----------------
__global__ void k_minmax(const float* __restrict__ z, const float* __restrict__ cl,
                         int nz, int ncl) {
    __shared__ unsigned slo[F], shi[F];
    int tid = threadIdx.x;
    if (tid < F) { slo[tid] = 0xFFFFFFFFu; shi[tid] = 0u; }
    __syncthreads();

    int gid = blockIdx.x * blockDim.x + tid;
    int stride = gridDim.x * blockDim.x;           // multiple of 16 -> feature stays fixed
    int total = nz + ncl;                          // nz is a multiple of 16
    unsigned lmin = 0xFFFFFFFFu, lmax = 0u;
    for (int i = gid; i < total; i += stride) {
        float v = (i < nz) ? z[i] : cl[i - nz];
        unsigned m = f2ord(v);
        lmin = min(lmin, m);
        lmax = max(lmax, m);
    }
    int f = gid & (F - 1);
    atomicMin(&slo[f], lmin);
    atomicMax(&shi[f], lmax);
    __syncthreads();
    if (tid < F) {
        atomicMin(&g_lo_bits[tid], slo[tid]);
        atomicMax(&g_hi_bits[tid], shi[tid]);
    }
}

// ---------------- 3) edges = lo + (hi-lo) * (b * 0.01f)  (linspace f32 semantics) ----------------
__global__ void k_edges() {
    int i = blockIdx.x * blockDim.x + threadIdx.x;
    if (i < F * NE) {
        int f = i / NE, b = i % NE;
        float lo = ord2f(g_lo_bits[f]);
        float hi = ord2f(g_hi_bits[f]);
        float t = (float)b * 0.01f;
        g_edges[i] = lo + (hi - lo) * t;
    }
}

// ---------------- 4) binary-search bins + histogram (combined), store sample/cluster bins ----------------
__global__ void k_bins(const float* __restrict__ z, const float* __restrict__ cl,
                       int nz, int ncl) {
    __shared__ float se[F * NE];
    __shared__ int   sh[F * NB];
    int tid = threadIdx.x;
    for (int i = tid; i < F * NE; i += blockDim.x) se[i] = g_edges[i];
    for (int i = tid; i < F * NB; i += blockDim.x) sh[i] = 0;
    __syncthreads();

    int total = nz + ncl;
    int gid = blockIdx.x * blockDim.x + tid;
    int stride = gridDim.x * blockDim.x;
    for (int i = gid; i < total; i += stride) {
        float v = (i < nz) ? z[i] : cl[i - nz];
        int f = i & (F - 1);
        const float* e = se + f * NE;
        // lower_bound: first idx with e[idx] >= v  (== searchsorted side='left')
        int L = 0, R = NE;
        while (L < R) {
            int m = (L + R) >> 1;
            if (e[m] < v) L = m + 1; else R = m;
        }
        int left = L;
        // side='right' = first idx with e[idx] > v (edges strictly increasing in practice)
        int right = left + ((left < NE && e[left] == v) ? 1 : 0);

        int hb = right - 1; hb = max(hb, 0); hb = min(hb, NB - 1);   // histogram bin (right, clipped)
        atomicAdd(&sh[f * NB + hb], 1);

        int sb = left - 1; sb = max(sb, 0); sb = min(sb, NB - 1);    // left bin (-1≡0, 100≡99)
        if (i < nz) g_sbins[i] = (unsigned char)sb;
        else        g_cbins[i - nz] = (unsigned char)sb;
    }
    __syncthreads();
    for (int i = tid; i < F * NB; i += blockDim.x) {
        int c = sh[i];
        if (c) atomicAdd(&g_counts[i], c);
    }
}

// ---------------- 5) inclusive scan of counts per feature (exact int) ----------------
__global__ void k_scan() {
    __shared__ int s[128];
    int f = blockIdx.x;
    int i = threadIdx.x;
    s[i] = (i < NB) ? g_counts[f * NB + i] : 0;
    __syncthreads();
    for (int off = 1; off < 128; off <<= 1) {
        int v = (i >= off) ? s[i - off] : 0;
        __syncthreads();
        s[i] += v;
        __syncthreads();
    }
    if (i < NB) g_cum[f * NB + i] = s[i];
}

// ---------------- 6) T[f][bs][c] = ((cum[mx] - (mn>0 ? cum[mn-1] : 0)) / divisor)^2 ----------------
__global__ void k_table(float inv_div) {
    __shared__ int sc[NB];
    __shared__ int scb[CNUM];
    int f = blockIdx.x;
    int tid = threadIdx.x;
    if (tid < NB)   sc[tid]  = g_cum[f * NB + tid];
    if (tid < CNUM) scb[tid] = g_cbins[tid * F + f];
    __syncthreads();
    for (int j = tid; j < NB * CNUM; j += blockDim.x) {
        int bs = j >> 4, c = j & 15;
        int cb = scb[c];
        int mn = min(bs, cb), mx = max(bs, cb);
        int sum = sc[mx] - ((mn > 0) ? sc[mn - 1] : 0);
        float s = (float)sum * inv_div;
        g_table[(f * NB + bs) * TPAD + c] = s * s;
    }
}

// ---------------- 7) main: per row gather 16x float4 from smem table, reduce, normalize ----------------
__global__ void __launch_bounds__(768) k_main(float* __restrict__ out, int nrows) {
    extern __shared__ float stab[];

    // issue the bins load early (independent of smem staging)
    int r = blockIdx.x * blockDim.x + threadIdx.x;
    bool active = (r < nrows);
    uint4 bw = make_uint4(0, 0, 0, 0);
    if (active) bw = *reinterpret_cast<const uint4*>(g_sbins + (size_t)r * 16);

    {   // stage the 125 KB table into shared memory
        const float4* src = reinterpret_cast<const float4*>(g_table);
        float4* dst = reinterpret_cast<float4*>(stab);
        const int n4 = F * NB * TPAD / 4;   // 8000
        for (int i = threadIdx.x; i < n4; i += blockDim.x) dst[i] = src[i];
    }
    __syncthreads();
    if (!active) return;

    unsigned w0 = bw.x, w1 = bw.y, w2 = bw.z, w3 = bw.w;
    float acc[16];
#pragma unroll
    for (int c = 0; c < 16; c++) acc[c] = 0.0f;

#pragma unroll
    for (int f = 0; f < 16; f++) {
        unsigned wsel = (f < 4) ? w0 : (f < 8) ? w1 : (f < 12) ? w2 : w3;
        unsigned b = (wsel >> ((f & 3) * 8)) & 0xFFu;
        const float4* tp = reinterpret_cast<const float4*>(stab + (f * NB + b) * TPAD);
        float4 t0 = tp[0], t1 = tp[1], t2 = tp[2], t3 = tp[3];
        acc[0]  += t0.x; acc[1]  += t0.y; acc[2]  += t0.z; acc[3]  += t0.w;
        acc[4]  += t1.x; acc[5]  += t1.y; acc[6]  += t1.z; acc[7]  += t1.w;
        acc[8]  += t2.x; acc[9]  += t2.y; acc[10] += t2.z; acc[11] += t2.w;
        acc[12] += t3.x; acc[13] += t3.y; acc[14] += t3.z; acc[15] += t3.w;
    }

    float ssum = 0.0f;
#pragma unroll
    for (int c = 0; c < 16; c++) {
        float m = sqrtf(acc[c]);
        float qc = __fdividef(1.0f, 1.0f + m);
        acc[c] = qc;                 // reuse registers
        ssum += qc;
    }
    float inv = __fdividef(1.0f, ssum);

    float* op = out + (size_t)r * 16;
#pragma unroll
    for (int k = 0; k < 4; k++) {
        float4 o;
        o.x = acc[4 * k + 0] * inv;
        o.y = acc[4 * k + 1] * inv;
        o.z = acc[4 * k + 2] * inv;
        o.w = acc[4 * k + 3] * inv;
        reinterpret_cast<float4*>(op)[k] = o;
    }
}

// ---------------- launch ----------------
extern "C" void kernel_launch(void* const* d_in, const int* in_sizes, int n_in,
                              void* d_out, int out_size) {
    const float* z  = (const float*)d_in[0];
    const float* cl = (const float*)d_in[1];
    int nz  = in_sizes[0];      // 1,600,000
    int ncl = in_sizes[1];      // 256
    int nrows = nz / F;         // 100,000
    float inv_div = 1.0f / (float)(nrows + ncl / F);   // 1 / 100016

    k_init<<<(F * NB + 255) / 256, 256>>>();
    k_minmax<<<256, 256>>>(z, cl, nz, ncl);
    k_edges<<<(F * NE + 255) / 256, 256>>>();
    k_bins<<<256, 256>>>(z, cl, nz, ncl);
    k_scan<<<F, 128>>>();
    k_table<<<F, 256>>>(inv_div);

    const int MAIN_BLK = 768;
    const int smem_bytes = F * NB * TPAD * (int)sizeof(float);   // 128,000 B
    cudaFuncSetAttribute(k_main, cudaFuncAttributeMaxDynamicSharedMemorySize, smem_bytes);
    int grid = (nrows + MAIN_BLK - 1) / MAIN_BLK;                // 131 CTAs
    k_main<<<grid, MAIN_BLK, smem_bytes>>>((float*)d_out, nrows);
}

// round 15
// speedup vs baseline: 1.0561x; 1.0561x over previous
#include <cuda_runtime.h>
#include <stdint.h>

// Problem constants (fixed by the reference: z[100000,16], cluster[16,16], 100 bins)
#define NMAX 100000
#define F    16
#define CNUM 16
#define NB   100
#define NE   101
#define TPAD 20   // floats per (f,bs) row in the lookup table (bank-conflict padding)

// ---------------- device scratch (no allocations allowed) ----------------
__device__ unsigned int g_lo_bits[F];
__device__ unsigned int g_hi_bits[F];
__device__ float        g_edges[F * NE];
__device__ int          g_counts[F * NB];
__device__ int          g_cum[F * NB];
__device__ __align__(16) unsigned char g_sbins[NMAX * F];
__device__ unsigned char g_cbins[CNUM * F];
__device__ __align__(16) float g_table[F * NB * TPAD];

// order-preserving float <-> uint map (handles negatives) for atomic min/max
__device__ __forceinline__ unsigned f2ord(float f) {
    unsigned u = __float_as_uint(f);
    return (u & 0x80000000u) ? ~u : (u | 0x80000000u);
}
__device__ __forceinline__ float ord2f(unsigned u) {
    return (u & 0x80000000u) ? __uint_as_float(u & 0x7fffffffu)
                             : __uint_as_float(~u);
}

// ---------------- 1) init sentinels + zero histogram ----------------
__global__ void k_init() {
    int i = blockIdx.x * blockDim.x + threadIdx.x;
    if (i < F * NB) g_counts[i] = 0;
    if (i < F) { g_lo_bits[i] = 0xFFFFFFFFu; g_hi_bits[i] = 0u; }
}

// ---------------- 2) per-feature min/max over combined = [z; cluster] ----------------
__global__ void k_minmax(const float* __restrict__ z, const float* __restrict__ cl,
                         int nz, int ncl) {
    __shared__ unsigned slo[F], shi[F];
    int tid = threadIdx.x;
    if (tid < F) { slo[tid] = 0xFFFFFFFFu; shi[tid] = 0u; }
    __syncthreads();

    int gid = blockIdx.x * blockDim.x + tid;
    int stride = gridDim.x * blockDim.x;           // multiple of 16 -> feature stays fixed
    int total = nz + ncl;                          // nz is a multiple of 16
    unsigned lmin = 0xFFFFFFFFu, lmax = 0u;
    for (int i = gid; i < total; i += stride) {
        float v = (i < nz) ? z[i] : cl[i - nz];
        unsigned m = f2ord(v);
        lmin = min(lmin, m);
        lmax = max(lmax, m);
    }
    int f = gid & (F - 1);
    atomicMin(&slo[f], lmin);
    atomicMax(&shi[f], lmax);
    __syncthreads();
    if (tid < F) {
        atomicMin(&g_lo_bits[tid], slo[tid]);
        atomicMax(&g_hi_bits[tid], shi[tid]);
    }
}

// ---------------- 3) edges = lo + (hi-lo) * (b * 0.01f)  (linspace f32 semantics) ----------------
__global__ void k_edges() {
    int i = blockIdx.x * blockDim.x + threadIdx.x;
    if (i < F * NE) {
        int f = i / NE, b = i % NE;
        float lo = ord2f(g_lo_bits[f]);
        float hi = ord2f(g_hi_bits[f]);
        float t = (float)b * 0.01f;
        g_edges[i] = lo + (hi - lo) * t;
    }
}

// ---------------- 4) binary-search bins + histogram (combined), store sample/cluster bins ----------------
__global__ void k_bins(const float* __restrict__ z, const float* __restrict__ cl,
                       int nz, int ncl) {
    __shared__ float se[F * NE];
    __shared__ int   sh[F * NB];
    int tid = threadIdx.x;
    for (int i = tid; i < F * NE; i += blockDim.x) se[i] = g_edges[i];
    for (int i = tid; i < F * NB; i += blockDim.x) sh[i] = 0;
    __syncthreads();

    int total = nz + ncl;
    int gid = blockIdx.x * blockDim.x + tid;
    int stride = gridDim.x * blockDim.x;
    for (int i = gid; i < total; i += stride) {
        float v = (i < nz) ? z[i] : cl[i - nz];
        int f = i & (F - 1);
        const float* e = se + f * NE;
        // lower_bound: first idx with e[idx] >= v  (== searchsorted side='left')
        int L = 0, R = NE;
        while (L < R) {
            int m = (L + R) >> 1;
            if (e[m] < v) L = m + 1; else R = m;
        }
        int left = L;
        // side='right' = first idx with e[idx] > v (edges strictly increasing in practice)
        int right = left + ((left < NE && e[left] == v) ? 1 : 0);

        int hb = right - 1; hb = max(hb, 0); hb = min(hb, NB - 1);   // histogram bin (right, clipped)
        atomicAdd(&sh[f * NB + hb], 1);

        int sb = left - 1; sb = max(sb, 0); sb = min(sb, NB - 1);    // left bin (-1≡0, 100≡99)
        if (i < nz) g_sbins[i] = (unsigned char)sb;
        else        g_cbins[i - nz] = (unsigned char)sb;
    }
    __syncthreads();
    for (int i = tid; i < F * NB; i += blockDim.x) {
        int c = sh[i];
        if (c) atomicAdd(&g_counts[i], c);
    }
}

// ---------------- 5) inclusive scan of counts per feature (exact int) ----------------
__global__ void k_scan() {
    __shared__ int s[128];
    int f = blockIdx.x;
    int i = threadIdx.x;
    s[i] = (i < NB) ? g_counts[f * NB + i] : 0;
    __syncthreads();
    for (int off = 1; off < 128; off <<= 1) {
        int v = (i >= off) ? s[i - off] : 0;
        __syncthreads();
        s[i] += v;
        __syncthreads();
    }
    if (i < NB) g_cum[f * NB + i] = s[i];
}

// ---------------- 6) T[f][bs][c] = ((cum[mx] - (mn>0 ? cum[mn-1] : 0)) / divisor)^2 ----------------
__global__ void k_table(float inv_div) {
    __shared__ int sc[NB];
    __shared__ int scb[CNUM];
    int f = blockIdx.x;
    int tid = threadIdx.x;
    if (tid < NB)   sc[tid]  = g_cum[f * NB + tid];
    if (tid < CNUM) scb[tid] = g_cbins[tid * F + f];
    __syncthreads();
    for (int j = tid; j < NB * CNUM; j += blockDim.x) {
        int bs = j >> 4, c = j & 15;
        int cb = scb[c];
        int mn = min(bs, cb), mx = max(bs, cb);
        int sum = sc[mx] - ((mn > 0) ? sc[mn - 1] : 0);
        float s = (float)sum * inv_div;
        g_table[(f * NB + bs) * TPAD + c] = s * s;
    }
}

// ---------------- 7) main: per row gather 16x float4 from smem table, reduce, normalize ----------------
__global__ void __launch_bounds__(768) k_main(float* __restrict__ out, int nrows) {
    extern __shared__ float stab[];

    // issue the bins load early (independent of smem staging)
    int r = blockIdx.x * blockDim.x + threadIdx.x;
    bool active = (r < nrows);
    uint4 bw = make_uint4(0, 0, 0, 0);
    if (active) bw = *reinterpret_cast<const uint4*>(g_sbins + (size_t)r * 16);

    {   // stage the 125 KB table into shared memory
        const float4* src = reinterpret_cast<const float4*>(g_table);
        float4* dst = reinterpret_cast<float4*>(stab);
        const int n4 = F * NB * TPAD / 4;   // 8000
        for (int i = threadIdx.x; i < n4; i += blockDim.x) dst[i] = src[i];
    }
    __syncthreads();
    if (!active) return;

    unsigned w0 = bw.x, w1 = bw.y, w2 = bw.z, w3 = bw.w;
    float acc[16];
#pragma unroll
    for (int c = 0; c < 16; c++) acc[c] = 0.0f;

#pragma unroll
    for (int f = 0; f < 16; f++) {
        unsigned wsel = (f < 4) ? w0 : (f < 8) ? w1 : (f < 12) ? w2 : w3;
        unsigned b = (wsel >> ((f & 3) * 8)) & 0xFFu;
        const float4* tp = reinterpret_cast<const float4*>(stab + (f * NB + b) * TPAD);
        float4 t0 = tp[0], t1 = tp[1], t2 = tp[2], t3 = tp[3];
        acc[0]  += t0.x; acc[1]  += t0.y; acc[2]  += t0.z; acc[3]  += t0.w;
        acc[4]  += t1.x; acc[5]  += t1.y; acc[6]  += t1.z; acc[7]  += t1.w;
        acc[8]  += t2.x; acc[9]  += t2.y; acc[10] += t2.z; acc[11] += t2.w;
        acc[12] += t3.x; acc[13] += t3.y; acc[14] += t3.z; acc[15] += t3.w;
    }

    float ssum = 0.0f;
#pragma unroll
    for (int c = 0; c < 16; c++) {
        float m = sqrtf(acc[c]);
        float qc = __fdividef(1.0f, 1.0f + m);
        acc[c] = qc;                 // reuse registers
        ssum += qc;
    }
    float inv = __fdividef(1.0f, ssum);

    float* op = out + (size_t)r * 16;
#pragma unroll
    for (int k = 0; k < 4; k++) {
        float4 o;
        o.x = acc[4 * k + 0] * inv;
        o.y = acc[4 * k + 1] * inv;
        o.z = acc[4 * k + 2] * inv;
        o.w = acc[4 * k + 3] * inv;
        reinterpret_cast<float4*>(op)[k] = o;
    }
}

// ---------------- launch ----------------
extern "C" void kernel_launch(void* const* d_in, const int* in_sizes, int n_in,
                              void* d_out, int out_size) {
    const float* z  = (const float*)d_in[0];
    const float* cl = (const float*)d_in[1];
    int nz  = in_sizes[0];      // 1,600,000
    int ncl = in_sizes[1];      // 256
    int nrows = nz / F;         // 100,000
    float inv_div = 1.0f / (float)(nrows + ncl / F);   // 1 / 100016

    k_init<<<(F * NB + 255) / 256, 256>>>();
    k_minmax<<<256, 256>>>(z, cl, nz, ncl);
    k_edges<<<(F * NE + 255) / 256, 256>>>();
    k_bins<<<256, 256>>>(z, cl, nz, ncl);
    k_scan<<<F, 128>>>();
    k_table<<<F, 256>>>(inv_div);

    const int MAIN_BLK = 768;
    const int smem_bytes = F * NB * TPAD * (int)sizeof(float);   // 128,000 B
    cudaFuncSetAttribute(k_main, cudaFuncAttributeMaxDynamicSharedMemorySize, smem_bytes);
    int grid = (nrows + MAIN_BLK - 1) / MAIN_BLK;                // 131 CTAs
    k_main<<<grid, MAIN_BLK, smem_bytes>>>((float*)d_out, nrows);
}